// round 13
// baseline (speedup 1.0000x reference)
#include <cuda_runtime.h>
#include <cuda_bf16.h>
#include <cuda_fp16.h>
#include <cstdint>
#include <math.h>

// ---------------- problem shape ----------------
#define B_SZ 16384
#define C_SZ 4096
#define D_SZ 256
// logical K = 512 : A = [z^2 | z],  W = [iv | -2*mu*iv]

// ---------------- GEMM tile (R10 inner structure) ----------------
#define BM 128
#define BN 128
#define NKT 16             // k-tiles of 32
#define NTHREADS 128       // 4 warps, each owns a 64x64 output tile
#define NTILES 4096        // (B/128) * (C/128)
#define GRID_P 304         // persistent CTAs (2 per SM on 152-SM GB300)

#define A_TILE_U4 1536
#define W_TILE_U4 1536
#define STAGE_U4 (A_TILE_U4 + W_TILE_U4)            // 3072 -> 48KB
#define STAGE_BYTES (STAGE_U4 * 16)
#define NSTAGES 2
#define SMEM_BYTES (NSTAGES * STAGE_BYTES)          // 98304 -> 2 CTAs/SM

// -------- scratch (__device__ globals; no allocation allowed) --------
__device__ uint4 g_A[(size_t)128 * NKT * A_TILE_U4];  // 48 MB
__device__ uint4 g_W[(size_t)32 * NKT * W_TILE_U4];   // 12 MB
__device__ float g_constc[C_SZ];                      // folded: -0.5*const_c + OFF

// ---------------- helpers ----------------
#define FP16_MIN_NORMAL 6.104e-5f

__device__ __forceinline__ float fp16_hi(float x) {
    if (fabsf(x) < FP16_MIN_NORMAL) return 0.0f;     // keep hi a NORMAL fp16 (or 0)
    return __half2float(__float2half_rn(x));
}
__device__ __forceinline__ uint32_t pack_h2(float e, float o) {
    __half2 t;
    t.x = (fabsf(e) < FP16_MIN_NORMAL) ? __half(0.0f) : __float2half_rn(e);
    t.y = (fabsf(o) < FP16_MIN_NORMAL) ? __half(0.0f) : __float2half_rn(o);
    return *(uint32_t*)&t;
}
__device__ __forceinline__ uint32_t pack_bf16(float e, float o) {
    __nv_bfloat162 t = __floats2bfloat162_rn(e, o);
    return *(uint32_t*)&t;
}
__device__ __forceinline__ uint32_t smem_u32(const void* p) {
    uint32_t a;
    asm("{ .reg .u64 t; cvta.to.shared.u64 t, %1; cvt.u32.u64 %0, t; }" : "=r"(a) : "l"(p));
    return a;
}
__device__ __forceinline__ void cp16(uint32_t dst, const void* src) {
    asm volatile("cp.async.cg.shared.global [%0], [%1], 16;" :: "r"(dst), "l"(src));
}
#define CP_COMMIT() asm volatile("cp.async.commit_group;" ::: "memory")
#define CP_WAIT1()  asm volatile("cp.async.wait_group 1;" ::: "memory")

__device__ __forceinline__ void mma_f16(float* d, const uint4& a, uint32_t b0, uint32_t b1) {
    asm volatile(
        "mma.sync.aligned.m16n8k16.row.col.f32.f16.f16.f32 "
        "{%0,%1,%2,%3}, {%4,%5,%6,%7}, {%8,%9}, {%0,%1,%2,%3};"
        : "+f"(d[0]), "+f"(d[1]), "+f"(d[2]), "+f"(d[3])
        : "r"(a.x), "r"(a.y), "r"(a.z), "r"(a.w), "r"(b0), "r"(b1));
}
__device__ __forceinline__ void mma_bf16(float* d, const uint4& a, uint32_t b0, uint32_t b1) {
    asm volatile(
        "mma.sync.aligned.m16n8k16.row.col.f32.bf16.bf16.f32 "
        "{%0,%1,%2,%3}, {%4,%5,%6,%7}, {%8,%9}, {%0,%1,%2,%3};"
        : "+f"(d[0]), "+f"(d[1]), "+f"(d[2]), "+f"(d[3])
        : "r"(a.x), "r"(a.y), "r"(a.z), "r"(a.w), "r"(b0), "r"(b1));
}

// logical operand values
__device__ __forceinline__ float Aval(const float* __restrict__ z, int r, int k) {
    float v = __ldg(z + (size_t)r * D_SZ + (k & 255));
    return (k < 256) ? v * v : v;
}
__device__ __forceinline__ float Wval(const float* __restrict__ mu,
                                      const float* __restrict__ lv, int c, int k) {
    int d = k & 255;
    float l = __ldg(lv + (size_t)c * D_SZ + d);
    float iv = expf(-l);
    return (k < 256) ? iv : -2.0f * __ldg(mu + (size_t)c * D_SZ + d) * iv;
}

// ---------------- ONE fused prep kernel ----------------
#define PREP_A_BLOCKS 4096
#define PREP_W_BLOCKS 1024
#define PREP_C_BLOCKS 4096
#define PREP_BLOCKS (PREP_A_BLOCKS + PREP_W_BLOCKS + PREP_C_BLOCKS)

__global__ void __launch_bounds__(256)
prep_all_kernel(const float* __restrict__ z,
                const float* __restrict__ mu,
                const float* __restrict__ logvar) {
    int blk = blockIdx.x;

    if (blk < PREP_A_BLOCKS) {
        int idx = blk * 256 + threadIdx.x;             // 1,048,576
        int lane = idx & 31, ks = (idx >> 5) & 1, mb = (idx >> 6) & 7;
        int kt = (idx >> 9) & 15, mt = idx >> 13;
        int grp = lane >> 2, tig = lane & 3;
        int r0 = mt * BM + mb * 16 + grp;
        int kbase = kt * 32 + ks * 16;
        int ke0 = kbase + tig * 2, ke1 = kbase + 8 + tig * 2;

        float a00 = Aval(z, r0, ke0),     a01 = Aval(z, r0, ke0 + 1);
        float a10 = Aval(z, r0 + 8, ke0), a11 = Aval(z, r0 + 8, ke0 + 1);
        float a20 = Aval(z, r0, ke1),     a21 = Aval(z, r0, ke1 + 1);
        float a30 = Aval(z, r0 + 8, ke1), a31 = Aval(z, r0 + 8, ke1 + 1);

        uint4 hi, lo, fl;
        hi.x = pack_h2(a00, a01); hi.y = pack_h2(a10, a11);
        hi.z = pack_h2(a20, a21); hi.w = pack_h2(a30, a31);
        lo.x = pack_bf16(a00 - fp16_hi(a00), a01 - fp16_hi(a01));
        lo.y = pack_bf16(a10 - fp16_hi(a10), a11 - fp16_hi(a11));
        lo.z = pack_bf16(a20 - fp16_hi(a20), a21 - fp16_hi(a21));
        lo.w = pack_bf16(a30 - fp16_hi(a30), a31 - fp16_hi(a31));
        fl.x = pack_bf16(a00, a01); fl.y = pack_bf16(a10, a11);
        fl.z = pack_bf16(a20, a21); fl.w = pack_bf16(a30, a31);

        size_t base = (size_t)(mt * NKT + kt) * A_TILE_U4;
        g_A[base + (mb * 2 + ks) * 32 + lane] = hi;
        g_A[base + 512 + (mb * 4 + ks) * 32 + lane] = lo;        // kb<2 : lo_a
        g_A[base + 512 + (mb * 4 + 2 + ks) * 32 + lane] = fl;    // kb>=2: full a

    } else if (blk < PREP_A_BLOCKS + PREP_W_BLOCKS) {
        int idx = (blk - PREP_A_BLOCKS) * 256 + threadIdx.x;   // 262,144
        int lane = idx & 31, ks = (idx >> 5) & 1, nbp = (idx >> 6) & 7;
        int kt = (idx >> 9) & 15, nt = idx >> 13;
        int grp = lane >> 2, tig = lane & 3;
        int c0 = nt * 128 + nbp * 16 + grp;
        int c1 = c0 + 8;
        int kbase = kt * 32 + ks * 16;
        int ke0 = kbase + tig * 2, ke1 = kbase + 8 + tig * 2;

        float w00 = Wval(mu, logvar, c0, ke0), w01 = Wval(mu, logvar, c0, ke0 + 1);
        float w10 = Wval(mu, logvar, c0, ke1), w11 = Wval(mu, logvar, c0, ke1 + 1);
        float w20 = Wval(mu, logvar, c1, ke0), w21 = Wval(mu, logvar, c1, ke0 + 1);
        float w30 = Wval(mu, logvar, c1, ke1), w31 = Wval(mu, logvar, c1, ke1 + 1);

        uint4 hi, fl, lo;
        hi.x = pack_h2(w00, w01); hi.y = pack_h2(w10, w11);
        hi.z = pack_h2(w20, w21); hi.w = pack_h2(w30, w31);
        fl.x = pack_bf16(w00, w01); fl.y = pack_bf16(w10, w11);
        fl.z = pack_bf16(w20, w21); fl.w = pack_bf16(w30, w31);
        lo.x = pack_bf16(w00 - fp16_hi(w00), w01 - fp16_hi(w01));
        lo.y = pack_bf16(w10 - fp16_hi(w10), w11 - fp16_hi(w11));
        lo.z = pack_bf16(w20 - fp16_hi(w20), w21 - fp16_hi(w21));
        lo.w = pack_bf16(w30 - fp16_hi(w30), w31 - fp16_hi(w31));

        size_t base = (size_t)(nt * NKT + kt) * W_TILE_U4;
        g_W[base + (nbp * 2 + ks) * 32 + lane] = hi;
        g_W[base + 512 + (nbp * 4 + ks) * 32 + lane] = fl;        // kb<2 : full w
        g_W[base + 512 + (nbp * 4 + 2 + ks) * 32 + lane] = lo;    // kb>=2: lo_w

    } else {
        int c = blk - PREP_A_BLOCKS - PREP_W_BLOCKS;
        int d = threadIdx.x;
        float lv = logvar[(size_t)c * D_SZ + d];
        float m  = mu[(size_t)c * D_SZ + d];
        float iv = expf(-lv);
        __shared__ float red[256];
        red[d] = fmaf(m * m, iv, lv);
        __syncthreads();
        #pragma unroll
        for (int s = 128; s > 0; s >>= 1) {
            if (d < s) red[d] += red[d + s];
            __syncthreads();
        }
        if (d == 0) {
            const float OFF = -235.24826450039622f - 8.317766166719343f;
            g_constc[c] = fmaf(-0.5f, red[0], OFF);   // folded
        }
    }
}

// ---------------- GEMM: persistent CTAs, 4 warps x (64x64), 2 CTAs/SM ----------------
__global__ void __launch_bounds__(NTHREADS, 2)
gemm_hybrid_kernel(float* __restrict__ out) {
    extern __shared__ uint4 smem4[];
    const int tid = threadIdx.x;
    const int lane = tid & 31;
    const int wid = tid >> 5;        // 0..3
    const int wm = wid >> 1;         // 0..1  (64-row band)
    const int wn = wid & 1;          // 0..1  (64-col band)
    const int grp = lane >> 2;
    const int tig = lane & 3;
    const uint32_t sb = smem_u32(smem4);

    const int G = gridDim.x;
    const int t0 = blockIdx.x;
    const int my_tiles = (NTILES - t0 + G - 1) / G;
    if (my_tiles <= 0) return;

    // bases for tile (linear id t): mt = t>>5, nt = t&31
    #define TILE_BASES(t, AB, WB)                                              \
        { int mt_ = (t) >> 5, nt_ = (t) & 31;                                  \
          AB = g_A + (size_t)mt_ * NKT * A_TILE_U4;                            \
          WB = g_W + (size_t)nt_ * NKT * W_TILE_U4; }

    #define LOAD_STAGE(slot, AB, WB, kt)                                       \
    {                                                                          \
        uint32_t s0 = sb + (uint32_t)(slot) * STAGE_BYTES;                     \
        const uint4* ag = (AB) + (size_t)(kt) * A_TILE_U4;                     \
        _Pragma("unroll")                                                      \
        for (int c = 0; c < 12; c++) {                                         \
            int id = tid + c * NTHREADS;                                       \
            cp16(s0 + (uint32_t)id * 16, ag + id);                             \
        }                                                                      \
        const uint4* wg = (WB) + (size_t)(kt) * W_TILE_U4;                     \
        uint32_t s1 = s0 + A_TILE_U4 * 16;                                     \
        _Pragma("unroll")                                                      \
        for (int c = 0; c < 12; c++) {                                         \
            int id = tid + c * NTHREADS;                                       \
            cp16(s1 + (uint32_t)id * 16, wg + id);                             \
        }                                                                      \
    }

    float acc[4][8][4];
    #pragma unroll
    for (int i = 0; i < 4; i++)
        #pragma unroll
        for (int j = 0; j < 8; j++)
            #pragma unroll
            for (int q = 0; q < 4; q++) acc[i][j][q] = 0.0f;

    const uint4 *Ab, *Wb;
    TILE_BASES(t0, Ab, Wb)
    LOAD_STAGE(0, Ab, Wb, 0) CP_COMMIT();
    LOAD_STAGE(1, Ab, Wb, 1) CP_COMMIT();

    for (int ti = 0; ti < my_tiles; ti++) {
        const int t = t0 + ti * G;
        const int mt = t >> 5, nt = t & 31;
        TILE_BASES(t, Ab, Wb)
        const uint4 *AbN = Ab, *WbN = Wb;
        const bool has_next = (ti + 1 < my_tiles);
        if (has_next) { TILE_BASES(t + G, AbN, WbN) }

        #pragma unroll
        for (int kt = 0; kt < NKT; kt++) {
            const int slot = kt & 1;
            CP_WAIT1();               // stage kt landed (kt+1 may fly)
            __syncthreads();

            const uint4* S   = smem4 + slot * STAGE_U4;
            const uint4* Afp = S;                     // [mb8][ks2][lane]
            const uint4* Abf = S + 512;               // [mb8][kb4][lane]
            const uint4* Wfp = S + A_TILE_U4;         // [nbp8][ks2][lane]
            const uint4* Wbf = S + A_TILE_U4 + 512;   // [nbp8][kb4][lane]

            // fp16 hi*hi : 2 k16 slices
            #pragma unroll
            for (int s = 0; s < 2; s++) {
                uint4 a[4], w[4];
                #pragma unroll
                for (int mf = 0; mf < 4; mf++)
                    a[mf] = Afp[((wm * 4 + mf) * 2 + s) * 32 + lane];
                #pragma unroll
                for (int p = 0; p < 4; p++)
                    w[p] = Wfp[((wn * 4 + p) * 2 + s) * 32 + lane];
                #pragma unroll
                for (int mf = 0; mf < 4; mf++)
                    #pragma unroll
                    for (int p = 0; p < 4; p++) {
                        mma_f16(acc[mf][2 * p],     a[mf], w[p].x, w[p].y);
                        mma_f16(acc[mf][2 * p + 1], a[mf], w[p].z, w[p].w);
                    }
            }
            // bf16 crosses: j0,1 = lo_a*w ; j2,3 = a*lo_w
            #pragma unroll
            for (int j = 0; j < 4; j++) {
                uint4 a[4], w[4];
                #pragma unroll
                for (int mf = 0; mf < 4; mf++)
                    a[mf] = Abf[((wm * 4 + mf) * 4 + j) * 32 + lane];
                #pragma unroll
                for (int p = 0; p < 4; p++)
                    w[p] = Wbf[((wn * 4 + p) * 4 + j) * 32 + lane];
                #pragma unroll
                for (int mf = 0; mf < 4; mf++)
                    #pragma unroll
                    for (int p = 0; p < 4; p++) {
                        mma_bf16(acc[mf][2 * p],     a[mf], w[p].x, w[p].y);
                        mma_bf16(acc[mf][2 * p + 1], a[mf], w[p].z, w[p].w);
                    }
            }

            __syncthreads();          // all warps done reading slot
            // issue stage kt+2: this tile, or spill into next tile's kt0/kt1
            if (kt < NKT - 2) {
                LOAD_STAGE(slot, Ab, Wb, kt + 2)
            } else if (has_next) {
                LOAD_STAGE(slot, AbN, WbN, kt - (NKT - 2))
            }
            CP_COMMIT();              // always commit (empty ok) for exact accounting

            // epilogue AFTER next-tile loads are in flight: stores overlap cp.async
            if (kt == NKT - 1) {
                const int m0 = mt * BM, n0 = nt * BN;
                #pragma unroll
                for (int mf = 0; mf < 4; mf++) {
                    #pragma unroll
                    for (int g = 0; g < 8; g++) {
                        int row = m0 + wm * 64 + mf * 16 + grp;
                        int col = n0 + wn * 64 + g * 8 + tig * 2;
                        float c0 = __ldg(g_constc + col);
                        float c1 = __ldg(g_constc + col + 1);
                        float2 o0, o1;
                        o0.x = fmaf(-0.5f, acc[mf][g][0], c0);
                        o0.y = fmaf(-0.5f, acc[mf][g][1], c1);
                        o1.x = fmaf(-0.5f, acc[mf][g][2], c0);
                        o1.y = fmaf(-0.5f, acc[mf][g][3], c1);
                        *(float2*)(out + (size_t)row * C_SZ + col)       = o0;
                        *(float2*)(out + (size_t)(row + 8) * C_SZ + col) = o1;
                    }
                }
                #pragma unroll
                for (int i = 0; i < 4; i++)
                    #pragma unroll
                    for (int j = 0; j < 8; j++)
                        #pragma unroll
                        for (int q = 0; q < 4; q++) acc[i][j][q] = 0.0f;
            }
        }
    }
}

// ---------------- softmax / argmax (smem row cache, exp cached) ----------------
__global__ void __launch_bounds__(256)
softmax_rows_kernel(const float* __restrict__ logits,
                    float* __restrict__ probs,
                    float* __restrict__ pred) {
    const int b = blockIdx.x, tid = threadIdx.x;
    __shared__ float row[C_SZ];
    __shared__ float sm[256]; __shared__ int si[256]; __shared__ float ss[256];

    const float4* src = (const float4*)(logits + (size_t)b * C_SZ);
    #pragma unroll
    for (int i = tid; i < C_SZ / 4; i += 256) ((float4*)row)[i] = src[i];
    __syncthreads();

    float m = -INFINITY; int mi = 0;
    #pragma unroll
    for (int k = 0; k < C_SZ / 256; k++) {
        int c = k * 256 + tid;
        float v = row[c];
        if (v > m) { m = v; mi = c; }
    }
    sm[tid] = m; si[tid] = mi;
    __syncthreads();
    #pragma unroll
    for (int s = 128; s > 0; s >>= 1) {
        if (tid < s) {
            if (sm[tid + s] > sm[tid] ||
                (sm[tid + s] == sm[tid] && si[tid + s] < si[tid])) {
                sm[tid] = sm[tid + s]; si[tid] = si[tid + s];
            }
        }
        __syncthreads();
    }
    const float rmax = sm[0];
    const int amax = si[0];
    __syncthreads();                  // sm/si reads done before row[] rewrite races? (row untouched) — guards sm reuse only

    // pass 2: exp in place + sum (exp computed ONCE)
    float s = 0.0f;
    #pragma unroll
    for (int k = 0; k < C_SZ / 256; k++) {
        int c = k * 256 + tid;
        float e = __expf(row[c] - rmax);
        row[c] = e;
        s += e;
    }
    ss[tid] = s;
    __syncthreads();
    #pragma unroll
    for (int st = 128; st > 0; st >>= 1) {
        if (tid < st) ss[tid] += ss[tid + st];
        __syncthreads();
    }
    const float inv = 1.0f / ss[0];

    // pass 3: scale + vectorized write
    float4* dst = (float4*)(probs + (size_t)b * C_SZ);
    #pragma unroll
    for (int k = 0; k < C_SZ / 1024; k++) {
        int i = k * 256 + tid;
        float4 e4 = ((const float4*)row)[i];
        e4.x *= inv; e4.y *= inv; e4.z *= inv; e4.w *= inv;
        dst[i] = e4;
    }
    if (tid == 0) pred[b] = (float)amax;
}

// ---------------- launch ----------------
extern "C" void kernel_launch(void* const* d_in, const int* in_sizes, int n_in,
                              void* d_out, int out_size) {
    const float* z      = (const float*)d_in[0];
    const float* mu     = (const float*)d_in[1];
    const float* logvar = (const float*)d_in[2];
    float* out = (float*)d_out;

    float* logits = out;
    float* probs  = out + (size_t)B_SZ * C_SZ;
    float* pred   = out + (size_t)2 * B_SZ * C_SZ;

    cudaFuncSetAttribute(gemm_hybrid_kernel,
                         cudaFuncAttributeMaxDynamicSharedMemorySize, SMEM_BYTES);

    prep_all_kernel<<<PREP_BLOCKS, 256>>>(z, mu, logvar);

    gemm_hybrid_kernel<<<GRID_P, NTHREADS, SMEM_BYTES>>>(logits);

    softmax_rows_kernel<<<B_SZ, 256>>>(logits, probs, pred);
}

// round 14
// speedup vs baseline: 1.0626x; 1.0626x over previous
#include <cuda_runtime.h>
#include <cuda_bf16.h>
#include <cuda_fp16.h>
#include <cstdint>
#include <math.h>

// ---------------- problem shape ----------------
#define B_SZ 16384
#define C_SZ 4096
#define D_SZ 256
// logical K = 512 : A = [z^2 | z],  W = [iv | -2*mu*iv]
// a*w = hi_a*hi_w + lo_a*hi_w + hi_a*lo_w  (all fp16 operands, fp32 accum)

// ---------------- GEMM tile ----------------
#define BM 128
#define BN 128
#define NKT 16             // k-tiles of 32
#define NTHREADS 128       // 4 warps, each owns a 64x64 output tile

// tile images (uint4 units): hi fp16 [mb8][ks2][lane] + lo fp16 same layout
#define A_TILE_U4 1024     // 512 hi + 512 lo -> 16KB
#define W_TILE_U4 1024
#define STAGE_U4 (A_TILE_U4 + W_TILE_U4)            // 2048 -> 32KB
#define STAGE_BYTES (STAGE_U4 * 16)
#define NSTAGES 2
#define SMEM_BYTES (NSTAGES * STAGE_BYTES)          // 65536 -> 2 CTAs/SM easily

// -------- scratch (__device__ globals; no allocation allowed) --------
__device__ uint4 g_A[(size_t)128 * NKT * A_TILE_U4];  // 32 MB
__device__ uint4 g_W[(size_t)32 * NKT * W_TILE_U4];   // 8 MB
__device__ float g_constc[C_SZ];                      // folded: -0.5*const_c + OFF

// ---------------- helpers ----------------
#define FP16_MIN_NORMAL 6.104e-5f

__device__ __forceinline__ float fp16_hi(float x) {
    if (fabsf(x) < FP16_MIN_NORMAL) return 0.0f;     // keep hi NORMAL fp16 (or 0)
    return __half2float(__float2half_rn(x));
}
// hi pack: clamp-to-zero below min normal (residual then carries the value)
__device__ __forceinline__ uint32_t pack_h2_hi(float e, float o) {
    __half2 t;
    t.x = (fabsf(e) < FP16_MIN_NORMAL) ? __half(0.0f) : __float2half_rn(e);
    t.y = (fabsf(o) < FP16_MIN_NORMAL) ? __half(0.0f) : __float2half_rn(o);
    return *(uint32_t*)&t;
}
// lo pack: raw round (subnormals fine/needed for residuals)
__device__ __forceinline__ uint32_t pack_h2_raw(float e, float o) {
    __half2 t = __floats2half2_rn(e, o);
    return *(uint32_t*)&t;
}
__device__ __forceinline__ uint32_t smem_u32(const void* p) {
    uint32_t a;
    asm("{ .reg .u64 t; cvta.to.shared.u64 t, %1; cvt.u32.u64 %0, t; }" : "=r"(a) : "l"(p));
    return a;
}
__device__ __forceinline__ void cp16(uint32_t dst, const void* src) {
    asm volatile("cp.async.cg.shared.global [%0], [%1], 16;" :: "r"(dst), "l"(src));
}
#define CP_COMMIT() asm volatile("cp.async.commit_group;" ::: "memory")
#define CP_WAIT1()  asm volatile("cp.async.wait_group 1;" ::: "memory")

__device__ __forceinline__ void mma_f16(float* d, const uint4& a, uint32_t b0, uint32_t b1) {
    asm volatile(
        "mma.sync.aligned.m16n8k16.row.col.f32.f16.f16.f32 "
        "{%0,%1,%2,%3}, {%4,%5,%6,%7}, {%8,%9}, {%0,%1,%2,%3};"
        : "+f"(d[0]), "+f"(d[1]), "+f"(d[2]), "+f"(d[3])
        : "r"(a.x), "r"(a.y), "r"(a.z), "r"(a.w), "r"(b0), "r"(b1));
}

// logical operand values
__device__ __forceinline__ float Aval(const float* __restrict__ z, int r, int k) {
    float v = __ldg(z + (size_t)r * D_SZ + (k & 255));
    return (k < 256) ? v * v : v;
}
__device__ __forceinline__ float Wval(const float* __restrict__ mu,
                                      const float* __restrict__ lv, int c, int k) {
    int d = k & 255;
    float l = __ldg(lv + (size_t)c * D_SZ + d);
    float iv = expf(-l);
    return (k < 256) ? iv : -2.0f * __ldg(mu + (size_t)c * D_SZ + d) * iv;
}

// ---------------- ONE fused prep kernel ----------------
#define PREP_A_BLOCKS 4096
#define PREP_W_BLOCKS 1024
#define PREP_C_BLOCKS 4096
#define PREP_BLOCKS (PREP_A_BLOCKS + PREP_W_BLOCKS + PREP_C_BLOCKS)

__global__ void __launch_bounds__(256)
prep_all_kernel(const float* __restrict__ z,
                const float* __restrict__ mu,
                const float* __restrict__ logvar) {
    int blk = blockIdx.x;

    if (blk < PREP_A_BLOCKS) {
        // A fragments: fields lane[0:5) ks[5:6) mb[6:9) kt[9:13) mt[13:)
        int idx = blk * 256 + threadIdx.x;             // 1,048,576
        int lane = idx & 31, ks = (idx >> 5) & 1, mb = (idx >> 6) & 7;
        int kt = (idx >> 9) & 15, mt = idx >> 13;
        int grp = lane >> 2, tig = lane & 3;
        int r0 = mt * BM + mb * 16 + grp;
        int kbase = kt * 32 + ks * 16;
        int ke0 = kbase + tig * 2, ke1 = kbase + 8 + tig * 2;

        float a00 = Aval(z, r0, ke0),     a01 = Aval(z, r0, ke0 + 1);
        float a10 = Aval(z, r0 + 8, ke0), a11 = Aval(z, r0 + 8, ke0 + 1);
        float a20 = Aval(z, r0, ke1),     a21 = Aval(z, r0, ke1 + 1);
        float a30 = Aval(z, r0 + 8, ke1), a31 = Aval(z, r0 + 8, ke1 + 1);

        uint4 hi, lo;
        hi.x = pack_h2_hi(a00, a01); hi.y = pack_h2_hi(a10, a11);
        hi.z = pack_h2_hi(a20, a21); hi.w = pack_h2_hi(a30, a31);
        lo.x = pack_h2_raw(a00 - fp16_hi(a00), a01 - fp16_hi(a01));
        lo.y = pack_h2_raw(a10 - fp16_hi(a10), a11 - fp16_hi(a11));
        lo.z = pack_h2_raw(a20 - fp16_hi(a20), a21 - fp16_hi(a21));
        lo.w = pack_h2_raw(a30 - fp16_hi(a30), a31 - fp16_hi(a31));

        size_t base = (size_t)(mt * NKT + kt) * A_TILE_U4;
        g_A[base + (mb * 2 + ks) * 32 + lane] = hi;
        g_A[base + 512 + (mb * 2 + ks) * 32 + lane] = lo;

    } else if (blk < PREP_A_BLOCKS + PREP_W_BLOCKS) {
        // W fragments: fields lane[0:5) ks[5:6) nbp[6:9) kt[9:13) nt[13:)
        int idx = (blk - PREP_A_BLOCKS) * 256 + threadIdx.x;   // 262,144
        int lane = idx & 31, ks = (idx >> 5) & 1, nbp = (idx >> 6) & 7;
        int kt = (idx >> 9) & 15, nt = idx >> 13;
        int grp = lane >> 2, tig = lane & 3;
        int c0 = nt * 128 + nbp * 16 + grp;
        int c1 = c0 + 8;
        int kbase = kt * 32 + ks * 16;
        int ke0 = kbase + tig * 2, ke1 = kbase + 8 + tig * 2;

        float w00 = Wval(mu, logvar, c0, ke0), w01 = Wval(mu, logvar, c0, ke0 + 1);
        float w10 = Wval(mu, logvar, c0, ke1), w11 = Wval(mu, logvar, c0, ke1 + 1);
        float w20 = Wval(mu, logvar, c1, ke0), w21 = Wval(mu, logvar, c1, ke0 + 1);
        float w30 = Wval(mu, logvar, c1, ke1), w31 = Wval(mu, logvar, c1, ke1 + 1);

        uint4 hi, lo;
        hi.x = pack_h2_hi(w00, w01); hi.y = pack_h2_hi(w10, w11);
        hi.z = pack_h2_hi(w20, w21); hi.w = pack_h2_hi(w30, w31);
        lo.x = pack_h2_raw(w00 - fp16_hi(w00), w01 - fp16_hi(w01));
        lo.y = pack_h2_raw(w10 - fp16_hi(w10), w11 - fp16_hi(w11));
        lo.z = pack_h2_raw(w20 - fp16_hi(w20), w21 - fp16_hi(w21));
        lo.w = pack_h2_raw(w30 - fp16_hi(w30), w31 - fp16_hi(w31));

        size_t base = (size_t)(nt * NKT + kt) * W_TILE_U4;
        g_W[base + (nbp * 2 + ks) * 32 + lane] = hi;
        g_W[base + 512 + (nbp * 2 + ks) * 32 + lane] = lo;

    } else {
        int c = blk - PREP_A_BLOCKS - PREP_W_BLOCKS;
        int d = threadIdx.x;
        float lv = logvar[(size_t)c * D_SZ + d];
        float m  = mu[(size_t)c * D_SZ + d];
        float iv = expf(-lv);
        __shared__ float red[256];
        red[d] = fmaf(m * m, iv, lv);
        __syncthreads();
        #pragma unroll
        for (int s = 128; s > 0; s >>= 1) {
            if (d < s) red[d] += red[d + s];
            __syncthreads();
        }
        if (d == 0) {
            const float OFF = -235.24826450039622f - 8.317766166719343f;
            g_constc[c] = fmaf(-0.5f, red[0], OFF);   // folded
        }
    }
}

// ---------------- GEMM: 4 warps x (64x64), 2 CTAs/SM, all-fp16 3-product ----------------
__global__ void __launch_bounds__(NTHREADS, 2)
gemm_hybrid_kernel(float* __restrict__ out) {
    extern __shared__ uint4 smem4[];
    const int tid = threadIdx.x;
    const int lane = tid & 31;
    const int wid = tid >> 5;        // 0..3
    const int wm = wid >> 1;         // 0..1  (64-row band)
    const int wn = wid & 1;          // 0..1  (64-col band)
    const int grp = lane >> 2;
    const int tig = lane & 3;

    const int nt = blockIdx.x;       // 0..31
    const int mt = blockIdx.y;       // 0..127
    const uint32_t sb = smem_u32(smem4);

    const uint4* Abase = g_A + (size_t)mt * NKT * A_TILE_U4;
    const uint4* Wbase = g_W + (size_t)nt * NKT * W_TILE_U4;

    #define LOAD_STAGE(slot, kt)                                               \
    {                                                                          \
        uint32_t s0 = sb + (uint32_t)(slot) * STAGE_BYTES;                     \
        const uint4* ag = Abase + (size_t)(kt) * A_TILE_U4;                    \
        _Pragma("unroll")                                                      \
        for (int c = 0; c < 8; c++) {                                          \
            int id = tid + c * NTHREADS;                                       \
            cp16(s0 + (uint32_t)id * 16, ag + id);                             \
        }                                                                      \
        const uint4* wg = Wbase + (size_t)(kt) * W_TILE_U4;                    \
        uint32_t s1 = s0 + A_TILE_U4 * 16;                                     \
        _Pragma("unroll")                                                      \
        for (int c = 0; c < 8; c++) {                                          \
            int id = tid + c * NTHREADS;                                       \
            cp16(s1 + (uint32_t)id * 16, wg + id);                             \
        }                                                                      \
    }

    float acc[4][8][4];              // [m-frag][n8 group][4]
    #pragma unroll
    for (int i = 0; i < 4; i++)
        #pragma unroll
        for (int j = 0; j < 8; j++)
            #pragma unroll
            for (int q = 0; q < 4; q++) acc[i][j][q] = 0.0f;

    LOAD_STAGE(0, 0) CP_COMMIT();
    LOAD_STAGE(1, 1) CP_COMMIT();

    for (int kt = 0; kt < NKT; kt++) {
        const int slot = kt & 1;
        CP_WAIT1();                   // stage kt landed (kt+1 may fly)
        __syncthreads();              // visible to all warps

        const uint4* S   = smem4 + slot * STAGE_U4;
        const uint4* Ahi = S;                     // [mb8][ks2][lane]
        const uint4* Alo = S + 512;
        const uint4* Whi = S + A_TILE_U4;         // [nbp8][ks2][lane]
        const uint4* Wlo = S + A_TILE_U4 + 512;

        #pragma unroll
        for (int s = 0; s < 2; s++) {
            uint4 ah[4], al[4], wh[4], wl[4];
            #pragma unroll
            for (int mf = 0; mf < 4; mf++) {
                ah[mf] = Ahi[((wm * 4 + mf) * 2 + s) * 32 + lane];
                al[mf] = Alo[((wm * 4 + mf) * 2 + s) * 32 + lane];
            }
            #pragma unroll
            for (int p = 0; p < 4; p++) {
                wh[p] = Whi[((wn * 4 + p) * 2 + s) * 32 + lane];
                wl[p] = Wlo[((wn * 4 + p) * 2 + s) * 32 + lane];
            }
            // hi*hi
            #pragma unroll
            for (int mf = 0; mf < 4; mf++)
                #pragma unroll
                for (int p = 0; p < 4; p++) {
                    mma_f16(acc[mf][2 * p],     ah[mf], wh[p].x, wh[p].y);
                    mma_f16(acc[mf][2 * p + 1], ah[mf], wh[p].z, wh[p].w);
                }
            // lo_a*hi_w
            #pragma unroll
            for (int mf = 0; mf < 4; mf++)
                #pragma unroll
                for (int p = 0; p < 4; p++) {
                    mma_f16(acc[mf][2 * p],     al[mf], wh[p].x, wh[p].y);
                    mma_f16(acc[mf][2 * p + 1], al[mf], wh[p].z, wh[p].w);
                }
            // hi_a*lo_w
            #pragma unroll
            for (int mf = 0; mf < 4; mf++)
                #pragma unroll
                for (int p = 0; p < 4; p++) {
                    mma_f16(acc[mf][2 * p],     ah[mf], wl[p].x, wl[p].y);
                    mma_f16(acc[mf][2 * p + 1], ah[mf], wl[p].z, wl[p].w);
                }
        }

        __syncthreads();              // all warps done reading slot
        if (kt + 2 < NKT) {
            LOAD_STAGE(slot, kt + 2)
            CP_COMMIT();
        }
    }

    // ---- epilogue (constc pre-folded with -0.5 and OFF) ----
    const int m0 = mt * BM, n0 = nt * BN;
    #pragma unroll
    for (int mf = 0; mf < 4; mf++) {
        #pragma unroll
        for (int g = 0; g < 8; g++) {
            int row = m0 + wm * 64 + mf * 16 + grp;
            int col = n0 + wn * 64 + g * 8 + tig * 2;
            float c0 = __ldg(g_constc + col);
            float c1 = __ldg(g_constc + col + 1);
            float2 o0, o1;
            o0.x = fmaf(-0.5f, acc[mf][g][0], c0);
            o0.y = fmaf(-0.5f, acc[mf][g][1], c1);
            o1.x = fmaf(-0.5f, acc[mf][g][2], c0);
            o1.y = fmaf(-0.5f, acc[mf][g][3], c1);
            *(float2*)(out + (size_t)row * C_SZ + col)       = o0;
            *(float2*)(out + (size_t)(row + 8) * C_SZ + col) = o1;
        }
    }
}

// ---------------- softmax / argmax (smem row cache, exp cached) ----------------
__global__ void __launch_bounds__(256)
softmax_rows_kernel(const float* __restrict__ logits,
                    float* __restrict__ probs,
                    float* __restrict__ pred) {
    const int b = blockIdx.x, tid = threadIdx.x;
    __shared__ float row[C_SZ];
    __shared__ float sm[256]; __shared__ int si[256]; __shared__ float ss[256];

    const float4* src = (const float4*)(logits + (size_t)b * C_SZ);
    #pragma unroll
    for (int i = tid; i < C_SZ / 4; i += 256) ((float4*)row)[i] = src[i];
    __syncthreads();

    float m = -INFINITY; int mi = 0;
    #pragma unroll
    for (int k = 0; k < C_SZ / 256; k++) {
        int c = k * 256 + tid;
        float v = row[c];
        if (v > m) { m = v; mi = c; }
    }
    sm[tid] = m; si[tid] = mi;
    __syncthreads();
    #pragma unroll
    for (int s = 128; s > 0; s >>= 1) {
        if (tid < s) {
            if (sm[tid + s] > sm[tid] ||
                (sm[tid + s] == sm[tid] && si[tid + s] < si[tid])) {
                sm[tid] = sm[tid + s]; si[tid] = si[tid + s];
            }
        }
        __syncthreads();
    }
    const float rmax = sm[0];
    const int amax = si[0];
    __syncthreads();

    // exp in place + sum (exp computed once)
    float s = 0.0f;
    #pragma unroll
    for (int k = 0; k < C_SZ / 256; k++) {
        int c = k * 256 + tid;
        float e = __expf(row[c] - rmax);
        row[c] = e;
        s += e;
    }
    ss[tid] = s;
    __syncthreads();
    #pragma unroll
    for (int st = 128; st > 0; st >>= 1) {
        if (tid < st) ss[tid] += ss[tid + st];
        __syncthreads();
    }
    const float inv = 1.0f / ss[0];

    float4* dst = (float4*)(probs + (size_t)b * C_SZ);
    #pragma unroll
    for (int k = 0; k < C_SZ / 1024; k++) {
        int i = k * 256 + tid;
        float4 e4 = ((const float4*)row)[i];
        e4.x *= inv; e4.y *= inv; e4.z *= inv; e4.w *= inv;
        dst[i] = e4;
    }
    if (tid == 0) pred[b] = (float)amax;
}

// ---------------- launch ----------------
extern "C" void kernel_launch(void* const* d_in, const int* in_sizes, int n_in,
                              void* d_out, int out_size) {
    const float* z      = (const float*)d_in[0];
    const float* mu     = (const float*)d_in[1];
    const float* logvar = (const float*)d_in[2];
    float* out = (float*)d_out;

    float* logits = out;
    float* probs  = out + (size_t)B_SZ * C_SZ;
    float* pred   = out + (size_t)2 * B_SZ * C_SZ;

    cudaFuncSetAttribute(gemm_hybrid_kernel,
                         cudaFuncAttributeMaxDynamicSharedMemorySize, SMEM_BYTES);

    prep_all_kernel<<<PREP_BLOCKS, 256>>>(z, mu, logvar);

    dim3 grid(C_SZ / BN, B_SZ / BM);       // (32, 128)
    gemm_hybrid_kernel<<<grid, NTHREADS, SMEM_BYTES>>>(logits);

    softmax_rows_kernel<<<B_SZ, 256>>>(logits, probs, pred);
}

// round 15
// speedup vs baseline: 1.0667x; 1.0038x over previous
#include <cuda_runtime.h>
#include <cuda_bf16.h>
#include <cuda_fp16.h>
#include <cstdint>
#include <math.h>

// ---------------- problem shape ----------------
#define B_SZ 16384
#define C_SZ 4096
#define D_SZ 256
// logical K = 512 : A = [z^2 | z],  W = [iv | -2*mu*iv]
// a*w = hi_a*hi_w + lo_a*hi_w + hi_a*lo_w  (all fp16 operands, fp32 accum)

// ---------------- GEMM tile ----------------
#define BM 128
#define BN 128
#define NKT 16             // k-tiles of 32
#define NTHREADS 128       // 4 warps, each owns a 64x64 output tile

// tile images (uint4 units): hi fp16 [mb8][ks2][lane] + lo fp16 same layout
#define A_TILE_U4 1024     // 512 hi + 512 lo -> 16KB
#define W_TILE_U4 1024
#define STAGE_U4 (A_TILE_U4 + W_TILE_U4)            // 2048 -> 32KB
#define STAGE_BYTES (STAGE_U4 * 16)
#define NSTAGES 2
#define SMEM_BYTES (NSTAGES * STAGE_BYTES)          // 65536 -> 2 CTAs/SM

// -------- scratch (__device__ globals; no allocation allowed) --------
__device__ uint4 g_A[(size_t)128 * NKT * A_TILE_U4];  // 32 MB
__device__ uint4 g_W[(size_t)32 * NKT * W_TILE_U4];   // 8 MB
__device__ float g_constc[C_SZ];                      // folded: -0.5*const_c + OFF

// ---------------- helpers ----------------
#define FP16_MIN_NORMAL 6.104e-5f

__device__ __forceinline__ float fp16_hi(float x) {
    if (fabsf(x) < FP16_MIN_NORMAL) return 0.0f;     // keep hi NORMAL fp16 (or 0)
    return __half2float(__float2half_rn(x));
}
__device__ __forceinline__ uint32_t pack_h2_hi(float e, float o) {
    __half2 t;
    t.x = (fabsf(e) < FP16_MIN_NORMAL) ? __half(0.0f) : __float2half_rn(e);
    t.y = (fabsf(o) < FP16_MIN_NORMAL) ? __half(0.0f) : __float2half_rn(o);
    return *(uint32_t*)&t;
}
__device__ __forceinline__ uint32_t pack_h2_raw(float e, float o) {
    __half2 t = __floats2half2_rn(e, o);
    return *(uint32_t*)&t;
}
__device__ __forceinline__ uint32_t smem_u32(const void* p) {
    uint32_t a;
    asm("{ .reg .u64 t; cvta.to.shared.u64 t, %1; cvt.u32.u64 %0, t; }" : "=r"(a) : "l"(p));
    return a;
}
__device__ __forceinline__ void cp16(uint32_t dst, const void* src) {
    asm volatile("cp.async.cg.shared.global [%0], [%1], 16;" :: "r"(dst), "l"(src));
}
#define CP_COMMIT() asm volatile("cp.async.commit_group;" ::: "memory")
#define CP_WAIT1()  asm volatile("cp.async.wait_group 1;" ::: "memory")

__device__ __forceinline__ void mma_f16(float* d, const uint4& a, uint32_t b0, uint32_t b1) {
    asm volatile(
        "mma.sync.aligned.m16n8k16.row.col.f32.f16.f16.f32 "
        "{%0,%1,%2,%3}, {%4,%5,%6,%7}, {%8,%9}, {%0,%1,%2,%3};"
        : "+f"(d[0]), "+f"(d[1]), "+f"(d[2]), "+f"(d[3])
        : "r"(a.x), "r"(a.y), "r"(a.z), "r"(a.w), "r"(b0), "r"(b1));
}

// logical operand values
__device__ __forceinline__ float Aval(const float* __restrict__ z, int r, int k) {
    float v = __ldg(z + (size_t)r * D_SZ + (k & 255));
    return (k < 256) ? v * v : v;
}
__device__ __forceinline__ float Wval(const float* __restrict__ mu,
                                      const float* __restrict__ lv, int c, int k) {
    int d = k & 255;
    float l = __ldg(lv + (size_t)c * D_SZ + d);
    float iv = expf(-l);
    return (k < 256) ? iv : -2.0f * __ldg(mu + (size_t)c * D_SZ + d) * iv;
}

// ---------------- ONE fused prep kernel ----------------
#define PREP_A_BLOCKS 4096
#define PREP_W_BLOCKS 1024
#define PREP_C_BLOCKS 4096
#define PREP_BLOCKS (PREP_A_BLOCKS + PREP_W_BLOCKS + PREP_C_BLOCKS)

__global__ void __launch_bounds__(256)
prep_all_kernel(const float* __restrict__ z,
                const float* __restrict__ mu,
                const float* __restrict__ logvar) {
    int blk = blockIdx.x;

    if (blk < PREP_A_BLOCKS) {
        // A fragments: fields lane[0:5) ks[5:6) mb[6:9) kt[9:13) mt[13:)
        int idx = blk * 256 + threadIdx.x;             // 1,048,576
        int lane = idx & 31, ks = (idx >> 5) & 1, mb = (idx >> 6) & 7;
        int kt = (idx >> 9) & 15, mt = idx >> 13;
        int grp = lane >> 2, tig = lane & 3;
        int r0 = mt * BM + mb * 16 + grp;
        int kbase = kt * 32 + ks * 16;
        int ke0 = kbase + tig * 2, ke1 = kbase + 8 + tig * 2;

        float a00 = Aval(z, r0, ke0),     a01 = Aval(z, r0, ke0 + 1);
        float a10 = Aval(z, r0 + 8, ke0), a11 = Aval(z, r0 + 8, ke0 + 1);
        float a20 = Aval(z, r0, ke1),     a21 = Aval(z, r0, ke1 + 1);
        float a30 = Aval(z, r0 + 8, ke1), a31 = Aval(z, r0 + 8, ke1 + 1);

        uint4 hi, lo;
        hi.x = pack_h2_hi(a00, a01); hi.y = pack_h2_hi(a10, a11);
        hi.z = pack_h2_hi(a20, a21); hi.w = pack_h2_hi(a30, a31);
        lo.x = pack_h2_raw(a00 - fp16_hi(a00), a01 - fp16_hi(a01));
        lo.y = pack_h2_raw(a10 - fp16_hi(a10), a11 - fp16_hi(a11));
        lo.z = pack_h2_raw(a20 - fp16_hi(a20), a21 - fp16_hi(a21));
        lo.w = pack_h2_raw(a30 - fp16_hi(a30), a31 - fp16_hi(a31));

        size_t base = (size_t)(mt * NKT + kt) * A_TILE_U4;
        g_A[base + (mb * 2 + ks) * 32 + lane] = hi;
        g_A[base + 512 + (mb * 2 + ks) * 32 + lane] = lo;

    } else if (blk < PREP_A_BLOCKS + PREP_W_BLOCKS) {
        // W fragments: fields lane[0:5) ks[5:6) nbp[6:9) kt[9:13) nt[13:)
        int idx = (blk - PREP_A_BLOCKS) * 256 + threadIdx.x;   // 262,144
        int lane = idx & 31, ks = (idx >> 5) & 1, nbp = (idx >> 6) & 7;
        int kt = (idx >> 9) & 15, nt = idx >> 13;
        int grp = lane >> 2, tig = lane & 3;
        int c0 = nt * 128 + nbp * 16 + grp;
        int c1 = c0 + 8;
        int kbase = kt * 32 + ks * 16;
        int ke0 = kbase + tig * 2, ke1 = kbase + 8 + tig * 2;

        float w00 = Wval(mu, logvar, c0, ke0), w01 = Wval(mu, logvar, c0, ke0 + 1);
        float w10 = Wval(mu, logvar, c0, ke1), w11 = Wval(mu, logvar, c0, ke1 + 1);
        float w20 = Wval(mu, logvar, c1, ke0), w21 = Wval(mu, logvar, c1, ke0 + 1);
        float w30 = Wval(mu, logvar, c1, ke1), w31 = Wval(mu, logvar, c1, ke1 + 1);

        uint4 hi, lo;
        hi.x = pack_h2_hi(w00, w01); hi.y = pack_h2_hi(w10, w11);
        hi.z = pack_h2_hi(w20, w21); hi.w = pack_h2_hi(w30, w31);
        lo.x = pack_h2_raw(w00 - fp16_hi(w00), w01 - fp16_hi(w01));
        lo.y = pack_h2_raw(w10 - fp16_hi(w10), w11 - fp16_hi(w11));
        lo.z = pack_h2_raw(w20 - fp16_hi(w20), w21 - fp16_hi(w21));
        lo.w = pack_h2_raw(w30 - fp16_hi(w30), w31 - fp16_hi(w31));

        size_t base = (size_t)(nt * NKT + kt) * W_TILE_U4;
        g_W[base + (nbp * 2 + ks) * 32 + lane] = hi;
        g_W[base + 512 + (nbp * 2 + ks) * 32 + lane] = lo;

    } else {
        int c = blk - PREP_A_BLOCKS - PREP_W_BLOCKS;
        int d = threadIdx.x;
        float lv = logvar[(size_t)c * D_SZ + d];
        float m  = mu[(size_t)c * D_SZ + d];
        float iv = expf(-lv);
        __shared__ float red[256];
        red[d] = fmaf(m * m, iv, lv);
        __syncthreads();
        #pragma unroll
        for (int s = 128; s > 0; s >>= 1) {
            if (d < s) red[d] += red[d + s];
            __syncthreads();
        }
        if (d == 0) {
            const float OFF = -235.24826450039622f - 8.317766166719343f;
            g_constc[c] = fmaf(-0.5f, red[0], OFF);   // folded
        }
    }
}

// ---------------- GEMM: 4 warps x (64x64), 2 CTAs/SM, all-fp16 3-product ----------------
__global__ void __launch_bounds__(NTHREADS, 2)
gemm_hybrid_kernel(float* __restrict__ out) {
    extern __shared__ uint4 smem4[];
    const int tid = threadIdx.x;
    const int lane = tid & 31;
    const int wid = tid >> 5;        // 0..3
    const int wm = wid >> 1;         // 0..1  (64-row band)
    const int wn = wid & 1;          // 0..1  (64-col band)
    const int grp = lane >> 2;
    const int tig = lane & 3;

    const int nt = blockIdx.x;       // 0..31
    const int mt = blockIdx.y;       // 0..127
    const uint32_t sb = smem_u32(smem4);

    const uint4* Abase = g_A + (size_t)mt * NKT * A_TILE_U4;
    const uint4* Wbase = g_W + (size_t)nt * NKT * W_TILE_U4;

    #define LOAD_STAGE(slot, kt)                                               \
    {                                                                          \
        uint32_t s0 = sb + (uint32_t)(slot) * STAGE_BYTES;                     \
        const uint4* ag = Abase + (size_t)(kt) * A_TILE_U4;                    \
        _Pragma("unroll")                                                      \
        for (int c = 0; c < 8; c++) {                                          \
            int id = tid + c * NTHREADS;                                       \
            cp16(s0 + (uint32_t)id * 16, ag + id);                             \
        }                                                                      \
        const uint4* wg = Wbase + (size_t)(kt) * W_TILE_U4;                    \
        uint32_t s1 = s0 + A_TILE_U4 * 16;                                     \
        _Pragma("unroll")                                                      \
        for (int c = 0; c < 8; c++) {                                          \
            int id = tid + c * NTHREADS;                                       \
            cp16(s1 + (uint32_t)id * 16, wg + id);                             \
        }                                                                      \
    }

    float acc[4][8][4];              // [m-frag][n8 group][4]
    #pragma unroll
    for (int i = 0; i < 4; i++)
        #pragma unroll
        for (int j = 0; j < 8; j++)
            #pragma unroll
            for (int q = 0; q < 4; q++) acc[i][j][q] = 0.0f;

    LOAD_STAGE(0, 0) CP_COMMIT();
    LOAD_STAGE(1, 1) CP_COMMIT();

    for (int kt = 0; kt < NKT; kt++) {
        const int slot = kt & 1;
        CP_WAIT1();                   // stage kt landed (kt+1 may fly)
        __syncthreads();              // visible to all warps

        const uint4* S   = smem4 + slot * STAGE_U4;
        const uint4* Ahi = S;                     // [mb8][ks2][lane]
        const uint4* Alo = S + 512;
        const uint4* Whi = S + A_TILE_U4;         // [nbp8][ks2][lane]
        const uint4* Wlo = S + A_TILE_U4 + 512;

        #pragma unroll
        for (int s = 0; s < 2; s++) {
            uint4 ah[4], al[4], wh[4], wl[4];
            #pragma unroll
            for (int mf = 0; mf < 4; mf++) {
                ah[mf] = Ahi[((wm * 4 + mf) * 2 + s) * 32 + lane];
                al[mf] = Alo[((wm * 4 + mf) * 2 + s) * 32 + lane];
            }
            #pragma unroll
            for (int p = 0; p < 4; p++) {
                wh[p] = Whi[((wn * 4 + p) * 2 + s) * 32 + lane];
                wl[p] = Wlo[((wn * 4 + p) * 2 + s) * 32 + lane];
            }
            // hi*hi
            #pragma unroll
            for (int mf = 0; mf < 4; mf++)
                #pragma unroll
                for (int p = 0; p < 4; p++) {
                    mma_f16(acc[mf][2 * p],     ah[mf], wh[p].x, wh[p].y);
                    mma_f16(acc[mf][2 * p + 1], ah[mf], wh[p].z, wh[p].w);
                }
            // lo_a*hi_w
            #pragma unroll
            for (int mf = 0; mf < 4; mf++)
                #pragma unroll
                for (int p = 0; p < 4; p++) {
                    mma_f16(acc[mf][2 * p],     al[mf], wh[p].x, wh[p].y);
                    mma_f16(acc[mf][2 * p + 1], al[mf], wh[p].z, wh[p].w);
                }
            // hi_a*lo_w
            #pragma unroll
            for (int mf = 0; mf < 4; mf++)
                #pragma unroll
                for (int p = 0; p < 4; p++) {
                    mma_f16(acc[mf][2 * p],     ah[mf], wl[p].x, wl[p].y);
                    mma_f16(acc[mf][2 * p + 1], ah[mf], wl[p].z, wl[p].w);
                }
        }

        __syncthreads();              // all warps done reading slot
        if (kt + 2 < NKT) {
            LOAD_STAGE(slot, kt + 2)
            CP_COMMIT();
        }
    }

    // ---- epilogue (constc pre-folded with -0.5 and OFF) ----
    const int m0 = mt * BM, n0 = nt * BN;
    #pragma unroll
    for (int mf = 0; mf < 4; mf++) {
        #pragma unroll
        for (int g = 0; g < 8; g++) {
            int row = m0 + wm * 64 + mf * 16 + grp;
            int col = n0 + wn * 64 + g * 8 + tig * 2;
            float c0 = __ldg(g_constc + col);
            float c1 = __ldg(g_constc + col + 1);
            float2 o0, o1;
            o0.x = fmaf(-0.5f, acc[mf][g][0], c0);
            o0.y = fmaf(-0.5f, acc[mf][g][1], c1);
            o1.x = fmaf(-0.5f, acc[mf][g][2], c0);
            o1.y = fmaf(-0.5f, acc[mf][g][3], c1);
            *(float2*)(out + (size_t)row * C_SZ + col)       = o0;
            *(float2*)(out + (size_t)(row + 8) * C_SZ + col) = o1;
        }
    }
}

// ---------------- softmax / argmax: REVERSED row order + streaming stores ----------------
__global__ void __launch_bounds__(256)
softmax_rows_kernel(const float* __restrict__ logits,
                    float* __restrict__ probs,
                    float* __restrict__ pred) {
    // Reverse mapping: first-scheduled blocks take the rows the GEMM wrote LAST,
    // which are still L2-resident (GEMM walks mt ascending; ~126MB of tail fits L2).
    const int b = (B_SZ - 1) - blockIdx.x;
    const int tid = threadIdx.x;
    __shared__ float row[C_SZ];
    __shared__ float sm[256]; __shared__ int si[256]; __shared__ float ss[256];

    const float4* src = (const float4*)(logits + (size_t)b * C_SZ);
    #pragma unroll
    for (int i = tid; i < C_SZ / 4; i += 256) ((float4*)row)[i] = src[i];
    __syncthreads();

    float m = -INFINITY; int mi = 0;
    #pragma unroll
    for (int k = 0; k < C_SZ / 256; k++) {
        int c = k * 256 + tid;
        float v = row[c];
        if (v > m) { m = v; mi = c; }
    }
    sm[tid] = m; si[tid] = mi;
    __syncthreads();
    #pragma unroll
    for (int s = 128; s > 0; s >>= 1) {
        if (tid < s) {
            if (sm[tid + s] > sm[tid] ||
                (sm[tid + s] == sm[tid] && si[tid + s] < si[tid])) {
                sm[tid] = sm[tid + s]; si[tid] = si[tid + s];
            }
        }
        __syncthreads();
    }
    const float rmax = sm[0];
    const int amax = si[0];
    __syncthreads();

    // exp in place + sum (exp computed once)
    float s = 0.0f;
    #pragma unroll
    for (int k = 0; k < C_SZ / 256; k++) {
        int c = k * 256 + tid;
        float e = __expf(row[c] - rmax);
        row[c] = e;
        s += e;
    }
    ss[tid] = s;
    __syncthreads();
    #pragma unroll
    for (int st = 128; st > 0; st >>= 1) {
        if (tid < st) ss[tid] += ss[tid + st];
        __syncthreads();
    }
    const float inv = 1.0f / ss[0];

    // scale + streaming write (probs never re-read: don't pollute L2)
    float4* dst = (float4*)(probs + (size_t)b * C_SZ);
    #pragma unroll
    for (int k = 0; k < C_SZ / 1024; k++) {
        int i = k * 256 + tid;
        float4 e4 = ((const float4*)row)[i];
        e4.x *= inv; e4.y *= inv; e4.z *= inv; e4.w *= inv;
        __stcs(dst + i, e4);
    }
    if (tid == 0) pred[b] = (float)amax;
}

// ---------------- launch ----------------
extern "C" void kernel_launch(void* const* d_in, const int* in_sizes, int n_in,
                              void* d_out, int out_size) {
    const float* z      = (const float*)d_in[0];
    const float* mu     = (const float*)d_in[1];
    const float* logvar = (const float*)d_in[2];
    float* out = (float*)d_out;

    float* logits = out;
    float* probs  = out + (size_t)B_SZ * C_SZ;
    float* pred   = out + (size_t)2 * B_SZ * C_SZ;

    cudaFuncSetAttribute(gemm_hybrid_kernel,
                         cudaFuncAttributeMaxDynamicSharedMemorySize, SMEM_BYTES);

    prep_all_kernel<<<PREP_BLOCKS, 256>>>(z, mu, logvar);

    dim3 grid(C_SZ / BN, B_SZ / BM);       // (32, 128)
    gemm_hybrid_kernel<<<grid, NTHREADS, SMEM_BYTES>>>(logits);

    softmax_rows_kernel<<<B_SZ, 256>>>(logits, probs, pred);
}